// round 1
// baseline (speedup 1.0000x reference)
#include <cuda_runtime.h>
#include <cuda_bf16.h>
#include <math.h>

// Problem constants (from reference setup_inputs)
#define MAXN 100000
#define MAXE 1600000
#define NGRAPH 512

// ------------------------- device scratch (no allocations allowed) ----------
__device__ float g_A[(size_t)MAXN * 128];   // GEMM output (hs = dinv * x@W)
__device__ float g_B[(size_t)MAXN * 128];   // aggregation output (BN input)
__device__ int   g_deg[MAXN];
__device__ int   g_tmp[MAXN];
__device__ int   g_rowptr[MAXN + 1];
__device__ int   g_cursor[MAXN];
__device__ int   g_col[MAXE];
__device__ float g_dinv[MAXN];
__device__ int   g_bsums[128];
__device__ float g_stats[1024];             // [0,64)=L1 [64,192)=L2 [192,448)=L3 [448,704)=L4
__device__ float g_pool[NGRAPH * 128];
__device__ float g_q[NGRAPH * 128];
__device__ float g_sc[4 * 128];             // per-layer BN scale  (offsets 0,128,256,384)
__device__ float g_sh[4 * 128];             // per-layer BN shift

// ------------------------------- setup kernels ------------------------------
__global__ void zero_kernel(int n) {
    int i = blockIdx.x * blockDim.x + threadIdx.x;
    if (i < n) g_deg[i] = 0;
    if (i < 1024) g_stats[i] = 0.f;
    if (i < NGRAPH * 128) g_pool[i] = 0.f;   // bits 0 == float 0; valid atomicMax init (ReLU>=0)
}

__global__ void deg_kernel(const int* __restrict__ dst, int e) {
    int i = blockIdx.x * blockDim.x + threadIdx.x;
    if (i < e) atomicAdd(&g_deg[dst[i]], 1);
}

// per-block inclusive scan of g_deg -> g_tmp, block sums -> g_bsums
__global__ void scan_block_kernel(int n) {
    __shared__ int s[1024];
    int i = blockIdx.x * 1024 + threadIdx.x;
    int v = (i < n) ? g_deg[i] : 0;
    s[threadIdx.x] = v;
    __syncthreads();
    for (int off = 1; off < 1024; off <<= 1) {
        int t = (threadIdx.x >= off) ? s[threadIdx.x - off] : 0;
        __syncthreads();
        s[threadIdx.x] += t;
        __syncthreads();
    }
    if (i < n) g_tmp[i] = s[threadIdx.x];
    if (threadIdx.x == 1023) g_bsums[blockIdx.x] = s[1023];
}

// exclusive scan of block sums (nb <= 128)
__global__ void scan_sums_kernel(int nb) {
    __shared__ int s[128];
    int t = threadIdx.x;
    int v = (t < nb) ? g_bsums[t] : 0;
    s[t] = v;
    __syncthreads();
    for (int off = 1; off < 128; off <<= 1) {
        int u = (t >= off) ? s[t - off] : 0;
        __syncthreads();
        s[t] += u;
        __syncthreads();
    }
    if (t < nb) g_bsums[t] = s[t] - v;   // exclusive
}

// finalize: rowptr, cursor, dinv
__global__ void scan_fin_kernel(int n) {
    int i = blockIdx.x * blockDim.x + threadIdx.x;
    if (i >= n) return;
    int incl = g_tmp[i] + g_bsums[i >> 10];
    g_rowptr[i + 1] = incl;
    g_cursor[i] = incl - g_deg[i];
    g_dinv[i] = rsqrtf((float)(g_deg[i] + 1));   // +1 self loop, always >= 1
    if (i == 0) g_rowptr[0] = 0;
}

__global__ void fill_kernel(const int* __restrict__ src, const int* __restrict__ dst, int e) {
    int i = blockIdx.x * blockDim.x + threadIdx.x;
    if (i < e) {
        int p = atomicAdd(&g_cursor[dst[i]], 1);
        g_col[p] = src[i];
    }
}

// ------------------------------- GEMM kernels --------------------------------
// Layer 1: x[N,6] @ W1[6,32], scaled by dinv -> g_A
__global__ void gemm1_kernel(const float* __restrict__ x, const float* __restrict__ W, int n) {
    __shared__ float Ws[6 * 32];
    int tid = threadIdx.x;
    if (tid < 6 * 32) Ws[tid] = W[tid];
    __syncthreads();
    int i = blockIdx.x * blockDim.x + tid;
    if (i >= n) return;
    float xv[6];
#pragma unroll
    for (int k = 0; k < 6; k++) xv[k] = x[(size_t)i * 6 + k];
    float dv = g_dinv[i];
    size_t base = (size_t)i * 32;
#pragma unroll
    for (int c = 0; c < 32; c++) {
        float acc = 0.f;
#pragma unroll
        for (int k = 0; k < 6; k++) acc = fmaf(xv[k], Ws[k * 32 + c], acc);
        g_A[base + c] = dv * acc;
    }
}

// Layer 2: relu(bn(g_B[N,32])) @ W2[32,64] * dinv -> g_A. Warp per node.
__global__ void gemm2_kernel(const float* __restrict__ W, int scoff, int n) {
    __shared__ float Ws[32 * 64];
    int tid = threadIdx.x;
    for (int i = tid; i < 32 * 64; i += blockDim.x) Ws[i] = W[i];
    __syncthreads();
    int lane = tid & 31;
    int gw = (blockIdx.x * blockDim.x + tid) >> 5;
    if (gw >= n) return;
    float xv = g_B[(size_t)gw * 32 + lane];
    xv = fmaxf(fmaf(g_sc[scoff + lane], xv, g_sh[scoff + lane]), 0.f);
    float a0 = 0.f, a1 = 0.f;
#pragma unroll
    for (int k = 0; k < 32; k++) {
        float v = __shfl_sync(0xffffffffu, xv, k);
        a0 = fmaf(v, Ws[k * 64 + lane], a0);
        a1 = fmaf(v, Ws[k * 64 + 32 + lane], a1);
    }
    float dv = g_dinv[gw];
    size_t base = (size_t)gw * 64;
    g_A[base + lane] = dv * a0;
    g_A[base + 32 + lane] = dv * a1;
}

// Layer 3: relu(bn(g_B[N,64])) @ W3[64,128] * dinv -> g_A. Warp per node.
__global__ void gemm3_kernel(const float* __restrict__ W, int scoff, int n) {
    __shared__ float Ws[64 * 128];
    int tid = threadIdx.x;
    for (int i = tid; i < 64 * 128; i += blockDim.x) Ws[i] = W[i];
    __syncthreads();
    int lane = tid & 31;
    int gw = (blockIdx.x * blockDim.x + tid) >> 5;
    if (gw >= n) return;
    float x0 = g_B[(size_t)gw * 64 + lane];
    float x1 = g_B[(size_t)gw * 64 + 32 + lane];
    x0 = fmaxf(fmaf(g_sc[scoff + lane], x0, g_sh[scoff + lane]), 0.f);
    x1 = fmaxf(fmaf(g_sc[scoff + 32 + lane], x1, g_sh[scoff + 32 + lane]), 0.f);
    float a0 = 0.f, a1 = 0.f, a2 = 0.f, a3 = 0.f;
#pragma unroll
    for (int k = 0; k < 32; k++) {
        float v = __shfl_sync(0xffffffffu, x0, k);
        const float* w = &Ws[k * 128];
        a0 = fmaf(v, w[lane], a0);
        a1 = fmaf(v, w[32 + lane], a1);
        a2 = fmaf(v, w[64 + lane], a2);
        a3 = fmaf(v, w[96 + lane], a3);
    }
#pragma unroll
    for (int k = 0; k < 32; k++) {
        float v = __shfl_sync(0xffffffffu, x1, k);
        const float* w = &Ws[(32 + k) * 128];
        a0 = fmaf(v, w[lane], a0);
        a1 = fmaf(v, w[32 + lane], a1);
        a2 = fmaf(v, w[64 + lane], a2);
        a3 = fmaf(v, w[96 + lane], a3);
    }
    float dv = g_dinv[gw];
    size_t base = (size_t)gw * 128;
    g_A[base + lane] = dv * a0;
    g_A[base + 32 + lane] = dv * a1;
    g_A[base + 64 + lane] = dv * a2;
    g_A[base + 96 + lane] = dv * a3;
}

// ---------------------------- aggregation kernels ----------------------------
// out[d] = dinv[d]*(sum_{in edges} hs[s] + hs[d]) + b ; accumulate BN sum/sumsq.
__global__ void agg32_kernel(const float* __restrict__ bias, int statoff, int n) {
    __shared__ float sred[64];
    int tid = threadIdx.x;
    if (tid < 64) sred[tid] = 0.f;
    __syncthreads();
    int lane = tid & 31;
    int nw = (gridDim.x * blockDim.x) >> 5;
    int gw = (blockIdx.x * blockDim.x + tid) >> 5;
    float b = bias[lane];
    float ps = 0.f, pq = 0.f;
    for (int d = gw; d < n; d += nw) {
        float acc = g_A[(size_t)d * 32 + lane];
        int beg = g_rowptr[d], end = g_rowptr[d + 1];
        for (int j = beg; j < end; j++) {
            int s = g_col[j];
            acc += g_A[(size_t)s * 32 + lane];
        }
        float o = fmaf(g_dinv[d], acc, b);
        g_B[(size_t)d * 32 + lane] = o;
        ps += o; pq += o * o;
    }
    atomicAdd(&sred[lane], ps);
    atomicAdd(&sred[32 + lane], pq);
    __syncthreads();
    if (tid < 64) atomicAdd(&g_stats[statoff + tid], sred[tid]);
}

__global__ void agg64_kernel(const float* __restrict__ bias, int statoff, int n) {
    __shared__ float sred[128];
    int tid = threadIdx.x;
    if (tid < 128) sred[tid] = 0.f;
    __syncthreads();
    int lane = tid & 31;
    int nw = (gridDim.x * blockDim.x) >> 5;
    int gw = (blockIdx.x * blockDim.x + tid) >> 5;
    int c0 = lane * 2;
    float b0 = bias[c0], b1 = bias[c0 + 1];
    float ps0 = 0.f, ps1 = 0.f, pq0 = 0.f, pq1 = 0.f;
    for (int d = gw; d < n; d += nw) {
        float2 acc = *(const float2*)&g_A[(size_t)d * 64 + c0];
        int beg = g_rowptr[d], end = g_rowptr[d + 1];
        for (int j = beg; j < end; j++) {
            int s = g_col[j];
            float2 v = *(const float2*)&g_A[(size_t)s * 64 + c0];
            acc.x += v.x; acc.y += v.y;
        }
        float dv = g_dinv[d];
        float o0 = fmaf(dv, acc.x, b0);
        float o1 = fmaf(dv, acc.y, b1);
        *(float2*)&g_B[(size_t)d * 64 + c0] = make_float2(o0, o1);
        ps0 += o0; ps1 += o1; pq0 += o0 * o0; pq1 += o1 * o1;
    }
    atomicAdd(&sred[c0], ps0);
    atomicAdd(&sred[c0 + 1], ps1);
    atomicAdd(&sred[64 + c0], pq0);
    atomicAdd(&sred[64 + c0 + 1], pq1);
    __syncthreads();
    for (int i = tid; i < 128; i += blockDim.x) atomicAdd(&g_stats[statoff + i], sred[i]);
}

__global__ void agg128_kernel(const float* __restrict__ bias, int statoff, int n) {
    __shared__ float sred[256];
    int tid = threadIdx.x;
    if (tid < 256) sred[tid] = 0.f;
    __syncthreads();
    int lane = tid & 31;
    int nw = (gridDim.x * blockDim.x) >> 5;
    int gw = (blockIdx.x * blockDim.x + tid) >> 5;
    int c0 = lane * 4;
    float4 b = *(const float4*)&bias[c0];
    float ps[4] = {0.f, 0.f, 0.f, 0.f};
    float pq[4] = {0.f, 0.f, 0.f, 0.f};
    for (int d = gw; d < n; d += nw) {
        float4 acc = *(const float4*)&g_A[(size_t)d * 128 + c0];
        int beg = g_rowptr[d], end = g_rowptr[d + 1];
        for (int j = beg; j < end; j++) {
            int s = g_col[j];
            float4 v = *(const float4*)&g_A[(size_t)s * 128 + c0];
            acc.x += v.x; acc.y += v.y; acc.z += v.z; acc.w += v.w;
        }
        float dv = g_dinv[d];
        float4 o;
        o.x = fmaf(dv, acc.x, b.x);
        o.y = fmaf(dv, acc.y, b.y);
        o.z = fmaf(dv, acc.z, b.z);
        o.w = fmaf(dv, acc.w, b.w);
        *(float4*)&g_B[(size_t)d * 128 + c0] = o;
        ps[0] += o.x; ps[1] += o.y; ps[2] += o.z; ps[3] += o.w;
        pq[0] += o.x * o.x; pq[1] += o.y * o.y; pq[2] += o.z * o.z; pq[3] += o.w * o.w;
    }
#pragma unroll
    for (int k = 0; k < 4; k++) {
        atomicAdd(&sred[c0 + k], ps[k]);
        atomicAdd(&sred[128 + c0 + k], pq[k]);
    }
    __syncthreads();
    for (int i = tid; i < 256; i += blockDim.x) atomicAdd(&g_stats[statoff + i], sred[i]);
}

// -------------------------- BN parameter computation --------------------------
__global__ void bnparams_kernel(int statoff, const float* __restrict__ gamma,
                                const float* __restrict__ beta, int scoff, int C, float invcnt) {
    int c = blockIdx.x * blockDim.x + threadIdx.x;
    if (c >= C) return;
    float m = g_stats[statoff + c] * invcnt;
    float var = g_stats[statoff + C + c] * invcnt - m * m;
    float inv = rsqrtf(var + 1e-5f);
    float s = gamma[c] * inv;
    g_sc[scoff + c] = s;
    g_sh[scoff + c] = fmaf(-m, s, beta[c]);
}

// ----------------------------------- pool ------------------------------------
__global__ void pool_kernel(const int* __restrict__ batch, int scoff, int n) {
    long long i = (long long)blockIdx.x * blockDim.x + threadIdx.x;
    if (i >= (long long)n * 128) return;
    int node = (int)(i >> 7);
    int c = (int)(i & 127);
    float v = fmaxf(fmaf(g_sc[scoff + c], g_B[i], g_sh[scoff + c]), 0.f);
    int g = batch[node];
    atomicMax((int*)&g_pool[g * 128 + c], __float_as_int(v));
}

// --------------------------------- final MLP ----------------------------------
__global__ void fc1_kernel(const float* __restrict__ Wf1, const float* __restrict__ bf1, int statoff) {
    __shared__ float pr[128];
    int g = blockIdx.x, t = threadIdx.x;
    pr[t] = g_pool[g * 128 + t];
    __syncthreads();
    float acc = bf1[t];
#pragma unroll 8
    for (int k = 0; k < 128; k++) acc = fmaf(pr[k], Wf1[k * 128 + t], acc);
    g_q[g * 128 + t] = acc;
    atomicAdd(&g_stats[statoff + t], acc);
    atomicAdd(&g_stats[statoff + 128 + t], acc * acc);
}

__global__ void fc2_kernel(const float* __restrict__ Wf2, const float* __restrict__ bf2,
                           int scoff, float* __restrict__ out) {
    __shared__ float r[128];
    __shared__ float red[64];
    int g = blockIdx.x, t = threadIdx.x;  // 64 threads
    r[t]      = fmaxf(fmaf(g_sc[scoff + t],      g_q[g * 128 + t],      g_sh[scoff + t]), 0.f);
    r[t + 64] = fmaxf(fmaf(g_sc[scoff + t + 64], g_q[g * 128 + t + 64], g_sh[scoff + t + 64]), 0.f);
    __syncthreads();
    float acc = bf2[t];
#pragma unroll 8
    for (int k = 0; k < 128; k++) acc = fmaf(r[k], Wf2[k * 64 + t], acc);
    red[t] = acc * acc;
    for (int off = 32; off > 0; off >>= 1) {
        __syncthreads();
        if (t < off) red[t] += red[t + off];
    }
    __syncthreads();
    float denom = fmaxf(sqrtf(red[0]), 1e-12f);
    out[g * 64 + t] = acc / denom;
}

// --------------------------------- launcher -----------------------------------
extern "C" void kernel_launch(void* const* d_in, const int* in_sizes, int n_in,
                              void* d_out, int out_size) {
    const float* x    = (const float*)d_in[0];
    const int* src    = (const int*)d_in[1];
    const int* dst    = (const int*)d_in[2];
    const int* batch  = (const int*)d_in[3];
    const float* W1  = (const float*)d_in[4];
    const float* b1  = (const float*)d_in[5];
    const float* G1  = (const float*)d_in[6];
    const float* be1 = (const float*)d_in[7];
    const float* W2  = (const float*)d_in[8];
    const float* b2  = (const float*)d_in[9];
    const float* G2  = (const float*)d_in[10];
    const float* be2 = (const float*)d_in[11];
    const float* W3  = (const float*)d_in[12];
    const float* b3  = (const float*)d_in[13];
    const float* G3  = (const float*)d_in[14];
    const float* be3 = (const float*)d_in[15];
    const float* Wf1 = (const float*)d_in[16];
    const float* bf1 = (const float*)d_in[17];
    const float* G4  = (const float*)d_in[18];
    const float* be4 = (const float*)d_in[19];
    const float* Wf2 = (const float*)d_in[20];
    const float* bf2 = (const float*)d_in[21];

    int n = in_sizes[0] / 6;
    int e = in_sizes[1];
    int nb = (n + 1023) / 1024;

    int zmax = n > NGRAPH * 128 ? n : NGRAPH * 128;
    zero_kernel<<<(zmax + 255) / 256, 256>>>(n);
    deg_kernel<<<(e + 255) / 256, 256>>>(dst, e);
    scan_block_kernel<<<nb, 1024>>>(n);
    scan_sums_kernel<<<1, 128>>>(nb);
    scan_fin_kernel<<<(n + 255) / 256, 256>>>(n);
    fill_kernel<<<(e + 255) / 256, 256>>>(src, dst, e);

    int wblocks = (n + 7) / 8;  // warp-per-node kernels, 256 threads

    // Layer 1
    gemm1_kernel<<<(n + 255) / 256, 256>>>(x, W1, n);
    agg32_kernel<<<2048, 256>>>(b1, 0, n);
    bnparams_kernel<<<1, 32>>>(0, G1, be1, 0, 32, 1.0f / (float)n);
    // Layer 2
    gemm2_kernel<<<wblocks, 256>>>(W2, 0, n);
    agg64_kernel<<<2048, 256>>>(b2, 64, n);
    bnparams_kernel<<<1, 64>>>(64, G2, be2, 128, 64, 1.0f / (float)n);
    // Layer 3
    gemm3_kernel<<<wblocks, 256>>>(W3, 128, n);
    agg128_kernel<<<2048, 256>>>(b3, 192, n);
    bnparams_kernel<<<1, 128>>>(192, G3, be3, 256, 128, 1.0f / (float)n);
    // Pool (bn3 + relu fused)
    long long pt = (long long)n * 128;
    pool_kernel<<<(int)((pt + 255) / 256), 256>>>(batch, 256, n);
    // MLP head
    fc1_kernel<<<NGRAPH, 128>>>(Wf1, bf1, 448);
    bnparams_kernel<<<1, 128>>>(448, G4, be4, 384, 128, 1.0f / 512.0f);
    fc2_kernel<<<NGRAPH, 64>>>(Wf2, bf2, 384, (float*)d_out);
}